// round 16
// baseline (speedup 1.0000x reference)
#include <cuda_runtime.h>
#include <cuda_fp16.h>
#include <cstdint>

// ---------------------------------------------------------------------------
// Problem dims
// ---------------------------------------------------------------------------
#define BB 8
#define UU 128
#define TT 256
#define EE 128
#define HH 128
#define NUM_STRIPS (BB * UU * 16)        // 16384 strips of 16 t-rows

// ---------------------------------------------------------------------------
// Device scratch (no allocs allowed)
// ---------------------------------------------------------------------------
__device__ __align__(16) float g_ue_proj[BB * UU * HH];     // ue @ W1u
__device__ __align__(16) float g_te_proj[BB * TT * HH];     // te @ W1t
__device__ __align__(16) float g_gcomb[BB * HH];            // ge @ W1g + b1
__device__ __align__(16) __half g_W2h[HH * HH];             // W2^T fp16 [n][k]
__device__ int g_tile_ctr;

// ---------------------------------------------------------------------------
// PTX helpers (plain sm_103-safe: ldmatrix + mma.sync + tanh.approx)
// ---------------------------------------------------------------------------
__device__ __forceinline__ uint32_t smem_to_u32(const void* p) {
    uint32_t a;
    asm("{ .reg .u64 t; cvta.to.shared.u64 t, %1; cvt.u32.u64 %0, t; }"
        : "=r"(a) : "l"(p));
    return a;
}

__device__ __forceinline__ void ldmatrix_x4(uint32_t& r0, uint32_t& r1,
                                            uint32_t& r2, uint32_t& r3,
                                            uint32_t addr) {
    asm volatile("ldmatrix.sync.aligned.m8n8.x4.shared.b16 {%0,%1,%2,%3}, [%4];"
                 : "=r"(r0), "=r"(r1), "=r"(r2), "=r"(r3) : "r"(addr));
}

__device__ __forceinline__ void mma_fp16(float* c, const uint32_t* a,
                                         const uint32_t* b) {
    asm volatile(
        "mma.sync.aligned.m16n8k16.row.col.f32.f16.f16.f32 "
        "{%0,%1,%2,%3}, {%4,%5,%6,%7}, {%8,%9}, {%0,%1,%2,%3};"
        : "+f"(c[0]), "+f"(c[1]), "+f"(c[2]), "+f"(c[3])
        : "r"(a[0]), "r"(a[1]), "r"(a[2]), "r"(a[3]), "r"(b[0]), "r"(b[1]));
}

// ---------------------------------------------------------------------------
// Math helpers
// ---------------------------------------------------------------------------
// Epilogue gelu: sigmoid form, 2 MUFU (ex2 + rcp) + ~5 FMA ops, fp32.
__device__ __forceinline__ float gelu_f(float x) {
    float s = x * x;
    float p = fmaf(s, 0.1029433f, 2.3022084f);
    float z = x * p;
    float e;
    asm("ex2.approx.ftz.f32 %0, %1;" : "=f"(e) : "f"(z));
    float d = e + 1.0f;
    float r;
    asm("rcp.approx.ftz.f32 %0, %1;" : "=f"(r) : "f"(d));
    return fmaf(-x, r, x);
}

// h1 gelu pair: tanh-form via tanh.approx.f16x2, returns packed half2.
__device__ __forceinline__ uint32_t gelu2_h2(float x0, float x1) {
    float z0 = x0 * fmaf(x0 * x0, 0.035677408f, 0.79788456f);
    float z1 = x1 * fmaf(x1 * x1, 0.035677408f, 0.79788456f);
    __half2 zh = __floats2half2_rn(z0, z1);
    uint32_t zb = *reinterpret_cast<uint32_t*>(&zh);
    uint32_t tb;
    asm("tanh.approx.f16x2 %0, %1;" : "=r"(tb) : "r"(zb));
    __half2 th = *reinterpret_cast<__half2*>(&tb);
    __half2 xh = __floats2half2_rn(x0, x1);
    const __half2 h05 = __half2half2(__float2half_rn(0.5f));
    __half2 y = __hmul2(xh, __hfma2(th, h05, h05));
    return *reinterpret_cast<uint32_t*>(&y);
}

// ---------------------------------------------------------------------------
// Prep kernel v3: 778 blocks x 256 threads, MLP-16 W-load chains.
//   0..255   : ue rows (4/block)   -> g_ue_proj
//   256..767 : te rows (4/block)   -> g_te_proj
//   768      : ge rows (8) + b1    -> g_gcomb
//   769..776 : W2 fp16 transpose   -> g_W2h ([n][k])
//   777      : tile counter reset
// ---------------------------------------------------------------------------
__global__ __launch_bounds__(256) void prep_kernel(
    const float* __restrict__ ue, const float* __restrict__ te,
    const float* __restrict__ ge, const float* __restrict__ W1,
    const float* __restrict__ b1, const float* __restrict__ W2) {
    __shared__ float s_in[8 * EE];
    const int bid = blockIdx.x;
    const int tid = threadIdx.x;

    if (bid < 768) {
        const float* src;
        float* dst;
        const float* W;
        if (bid < 256) {
            src = ue + bid * 4 * EE;  dst = g_ue_proj + bid * 4 * HH;  W = W1;
        } else {
            int r = bid - 256;
            src = te + r * 4 * EE;    dst = g_te_proj + r * 4 * HH;
            W = W1 + EE * HH;
        }
        for (int i = tid; i < 4 * EE; i += 256) s_in[i] = src[i];
        __syncthreads();

        const int col = tid & 127;
        const int rh  = (tid >> 7) * 2;              // rows rh, rh+1
        float a0 = 0.0f, a1 = 0.0f;
#pragma unroll 16
        for (int e = 0; e < EE; e++) {
            float w = W[e * HH + col];
            a0 = fmaf(s_in[(rh + 0) * EE + e], w, a0);
            a1 = fmaf(s_in[(rh + 1) * EE + e], w, a1);
        }
        dst[(rh + 0) * HH + col] = a0;
        dst[(rh + 1) * HH + col] = a1;
    } else if (bid == 768) {
        // ge (8 rows) + b1 -> g_gcomb
        for (int i = tid; i < 8 * EE; i += 256) s_in[i] = ge[i];
        __syncthreads();
        const float* W = W1 + 2 * EE * HH;
        const int col = tid & 127;
        const int rh  = (tid >> 7) * 4;              // rows rh..rh+3
        float bb = b1[col];
        float a0 = bb, a1 = bb, a2 = bb, a3 = bb;
#pragma unroll 16
        for (int e = 0; e < EE; e++) {
            float w = W[e * HH + col];
            a0 = fmaf(s_in[(rh + 0) * EE + e], w, a0);
            a1 = fmaf(s_in[(rh + 1) * EE + e], w, a1);
            a2 = fmaf(s_in[(rh + 2) * EE + e], w, a2);
            a3 = fmaf(s_in[(rh + 3) * EE + e], w, a3);
        }
        g_gcomb[(rh + 0) * HH + col] = a0;
        g_gcomb[(rh + 1) * HH + col] = a1;
        g_gcomb[(rh + 2) * HH + col] = a2;
        g_gcomb[(rh + 3) * HH + col] = a3;
    } else if (bid < 777) {
        const int n0 = (bid - 769) * 16 + (tid >> 7) * 8;
        const int k  = tid & 127;
#pragma unroll
        for (int j = 0; j < 8; j++)
            g_W2h[(n0 + j) * HH + k] = __float2half_rn(W2[k * HH + n0 + j]);
    } else {
        if (tid == 0) g_tile_ctr = 0;
    }
}

// ---------------------------------------------------------------------------
// Main fused kernel — R12/R15 verbatim: warp-autonomous 16-row strips,
// 2 CTAs/SM, f16x2-tanh h1 gelu, no block barriers in the loop.
// ---------------------------------------------------------------------------
static constexpr int ST      = 136;                 // row stride in fp16
static constexpr int STB     = ST * 2;              // 272 bytes
static constexpr int OFF_B   = 0;                   // 128 rows x STB = 34816
static constexpr int OFF_A   = 34816;               // 8 warps x 16 rows x STB
static constexpr int OFF_BW  = OFF_A + 34816;       // 128 x float2 (b2, W3)
static constexpr int SMEM_MAIN = OFF_BW + 1024;     // ~70.7 KB -> 2 CTAs/SM

__global__ __launch_bounds__(256, 2) void pairwise_main(
    const float* __restrict__ b2, const float* __restrict__ W3,
    const float* __restrict__ b3, float* __restrict__ out) {
    extern __shared__ char smem[];
    const uint32_t smem_base = smem_to_u32(smem);
    const int tid  = threadIdx.x;
    const int wid  = tid >> 5;
    const int lane = tid & 31;

    // Stage W2 (padded rows) + packed (b2, W3) pairs into SMEM, once.
    {
        const uint4* sb = (const uint4*)g_W2h;
        for (int i = tid; i < 2048; i += 256) {       // 128 rows x 16 uint4
            int r = i >> 4, c = i & 15;
            *(uint4*)(smem + OFF_B + r * STB + c * 16) = sb[i];
        }
        if (tid < 128)
            *(float2*)(smem + OFF_BW + tid * 8) = make_float2(b2[tid], W3[tid]);
    }
    const float bias3 = b3[0];
    __syncthreads();                                 // the only block barrier

    // Per-warp A buffer base
    const uint32_t abase_u = smem_base + OFF_A + wid * 16 * STB;
    char* abuf = smem + OFF_A + wid * 16 * STB + lane * 8;

    // ldmatrix lane addressing (within warp-private 16-row A / shared B)
    const uint32_t a_addr0 = abase_u + (lane & 15) * STB + ((lane >> 4) * 8) * 2;
    const int b_r = ((lane >> 4) & 1) * 8 + (lane & 7);
    const int b_k = ((lane >> 3) & 1) * 8;

    for (;;) {
        int s;
        if (lane == 0) s = atomicAdd(&g_tile_ctr, 1);
        s = __shfl_sync(0xffffffffu, s, 0);
        if (s >= NUM_STRIPS) break;

        const int b  = s >> 11;
        const int u  = (s >> 4) & 127;
        const int tq = s & 15;

        // per-lane uc columns 4l..4l+3 (registers)
        const float4 uev = *(const float4*)(g_ue_proj + (b * UU + u) * HH + (lane << 2));
        const float4 gcv = *(const float4*)(g_gcomb + b * HH + (lane << 2));
        const float4 ucv = make_float4(uev.x + gcv.x, uev.y + gcv.y,
                                       uev.z + gcv.z, uev.w + gcv.w);

        // ---- h1: 16 rows, coalesced LDG + f16x2-tanh gelu -> private A ----
        const float* tebase =
            g_te_proj + ((size_t)(b * TT + tq * 16)) * HH + (lane << 2);
#pragma unroll
        for (int r = 0; r < 16; r++) {
            float4 tv = *(const float4*)(tebase + (size_t)r * HH);
            uint32_t y01 = gelu2_h2(tv.x + ucv.x, tv.y + ucv.y);
            uint32_t y23 = gelu2_h2(tv.z + ucv.z, tv.w + ucv.w);
            *(uint2*)(abuf + r * STB) = make_uint2(y01, y23);
        }
        __syncwarp();

        // ---- GEMM: 16x128x128, acc[16 n-tiles][4] in regs ----
        float acc[16][4];
#pragma unroll
        for (int nt = 0; nt < 16; nt++)
#pragma unroll
            for (int i = 0; i < 4; i++) acc[nt][i] = 0.0f;

#pragma unroll
        for (int kt = 0; kt < 8; kt++) {
            const int k0 = kt * 16;
            uint32_t a[4];
            ldmatrix_x4(a[0], a[1], a[2], a[3], a_addr0 + k0 * 2);
            uint32_t bh[16][2];
#pragma unroll
            for (int np = 0; np < 8; np++) {          // pairs of n-tiles
                uint32_t baddr =
                    smem_base + OFF_B + (b_r + np * 16) * STB + (k0 + b_k) * 2;
                ldmatrix_x4(bh[np * 2][0], bh[np * 2][1],
                            bh[np * 2 + 1][0], bh[np * 2 + 1][1], baddr);
            }
#pragma unroll
            for (int nt = 0; nt < 16; nt++)
                mma_fp16(acc[nt], a, bh[nt]);
        }

        // ---- Epilogue: gelu(acc + b2) . W3 over N=128, direct STG ----
        float s0 = 0.0f, s1 = 0.0f;
#pragma unroll
        for (int nt = 0; nt < 16; nt++) {
            const int c0 = nt * 8 + 2 * (lane & 3);
            float4 bw = *(const float4*)(smem + OFF_BW + c0 * 8);
            s0 = fmaf(gelu_f(acc[nt][0] + bw.x), bw.y, s0);
            s0 = fmaf(gelu_f(acc[nt][1] + bw.z), bw.w, s0);
            s1 = fmaf(gelu_f(acc[nt][2] + bw.x), bw.y, s1);
            s1 = fmaf(gelu_f(acc[nt][3] + bw.z), bw.w, s1);
        }
        s0 += __shfl_xor_sync(0xffffffffu, s0, 1);
        s0 += __shfl_xor_sync(0xffffffffu, s0, 2);
        s1 += __shfl_xor_sync(0xffffffffu, s1, 1);
        s1 += __shfl_xor_sync(0xffffffffu, s1, 2);
        if ((lane & 3) == 0) {
            const int t0 = tq * 16 + (lane >> 2);
            float* o = out + (size_t)b * (UU * TT) + u * TT;
            o[t0]     = s0 + bias3;
            o[t0 + 8] = s1 + bias3;
        }
    }
}

// ---------------------------------------------------------------------------
// Launch
// ---------------------------------------------------------------------------
extern "C" void kernel_launch(void* const* d_in, const int* in_sizes, int n_in,
                              void* d_out, int out_size) {
    (void)in_sizes; (void)n_in; (void)out_size;
    const float* ue = (const float*)d_in[0];
    const float* te = (const float*)d_in[1];
    const float* ge = (const float*)d_in[2];
    const float* W1 = (const float*)d_in[3];
    const float* b1 = (const float*)d_in[4];
    const float* W2 = (const float*)d_in[5];
    const float* b2 = (const float*)d_in[6];
    const float* W3 = (const float*)d_in[7];
    const float* b3 = (const float*)d_in[8];
    float* out = (float*)d_out;

    cudaFuncSetAttribute(pairwise_main,
                         cudaFuncAttributeMaxDynamicSharedMemorySize, SMEM_MAIN);

    prep_kernel<<<778, 256>>>(ue, te, ge, W1, b1, W2);
    pairwise_main<<<304, 256, SMEM_MAIN>>>(b2, W3, b3, out);
}

// round 17
// speedup vs baseline: 1.0854x; 1.0854x over previous
#include <cuda_runtime.h>
#include <cuda_fp16.h>
#include <cstdint>

// ---------------------------------------------------------------------------
// Problem dims
// ---------------------------------------------------------------------------
#define BB 8
#define UU 128
#define TT 256
#define EE 128
#define HH 128
#define NUM_STRIPS (BB * UU * 16)        // 16384 strips of 16 t-rows

// ---------------------------------------------------------------------------
// Device scratch (no allocs allowed)
// ---------------------------------------------------------------------------
__device__ __align__(16) float g_ue_proj[BB * UU * HH];     // ue @ W1u
__device__ __align__(16) float g_te_proj[BB * TT * HH];     // te @ W1t
__device__ __align__(16) float g_gcomb[BB * HH];            // ge @ W1g + b1
__device__ __align__(16) __half g_W2h[HH * HH];             // W2^T fp16 [n][k]
__device__ int g_tile_ctr;

// ---------------------------------------------------------------------------
// PTX helpers (plain sm_103-safe: ldmatrix + mma.sync + tanh.approx)
// ---------------------------------------------------------------------------
__device__ __forceinline__ uint32_t smem_to_u32(const void* p) {
    uint32_t a;
    asm("{ .reg .u64 t; cvta.to.shared.u64 t, %1; cvt.u32.u64 %0, t; }"
        : "=r"(a) : "l"(p));
    return a;
}

__device__ __forceinline__ void ldmatrix_x4(uint32_t& r0, uint32_t& r1,
                                            uint32_t& r2, uint32_t& r3,
                                            uint32_t addr) {
    asm volatile("ldmatrix.sync.aligned.m8n8.x4.shared.b16 {%0,%1,%2,%3}, [%4];"
                 : "=r"(r0), "=r"(r1), "=r"(r2), "=r"(r3) : "r"(addr));
}

__device__ __forceinline__ void mma_fp16(float* c, const uint32_t* a,
                                         const uint32_t* b) {
    asm volatile(
        "mma.sync.aligned.m16n8k16.row.col.f32.f16.f16.f32 "
        "{%0,%1,%2,%3}, {%4,%5,%6,%7}, {%8,%9}, {%0,%1,%2,%3};"
        : "+f"(c[0]), "+f"(c[1]), "+f"(c[2]), "+f"(c[3])
        : "r"(a[0]), "r"(a[1]), "r"(a[2]), "r"(a[3]), "r"(b[0]), "r"(b[1]));
}

// ---------------------------------------------------------------------------
// Math helpers
// ---------------------------------------------------------------------------
// Epilogue gelu: tanh-form via tanh.approx.f32 — 1 MUFU + 5 FMA-pipe ops.
//   y = 0.5*x*(1 + tanh(x*(0.79788456 + 0.035677408*x^2)))
__device__ __forceinline__ float gelu_f(float x) {
    float z = x * fmaf(x * x, 0.035677408f, 0.79788456f);
    float t;
    asm("tanh.approx.f32 %0, %1;" : "=f"(t) : "f"(z));
    float hx = 0.5f * x;
    return fmaf(hx, t, hx);
}

// h1 gelu pair: tanh-form via tanh.approx.f16x2, returns packed half2.
__device__ __forceinline__ uint32_t gelu2_h2(float x0, float x1) {
    float z0 = x0 * fmaf(x0 * x0, 0.035677408f, 0.79788456f);
    float z1 = x1 * fmaf(x1 * x1, 0.035677408f, 0.79788456f);
    __half2 zh = __floats2half2_rn(z0, z1);
    uint32_t zb = *reinterpret_cast<uint32_t*>(&zh);
    uint32_t tb;
    asm("tanh.approx.f16x2 %0, %1;" : "=r"(tb) : "r"(zb));
    __half2 th = *reinterpret_cast<__half2*>(&tb);
    __half2 xh = __floats2half2_rn(x0, x1);
    const __half2 h05 = __half2half2(__float2half_rn(0.5f));
    __half2 y = __hmul2(xh, __hfma2(th, h05, h05));
    return *reinterpret_cast<uint32_t*>(&y);
}

// ---------------------------------------------------------------------------
// Prep kernel (R15 v2 — best measured): 394 blocks x 256 threads.
//   0..127   : ue rows (8/block)   -> g_ue_proj
//   128..383 : te rows (8/block)   -> g_te_proj
//   384      : ge rows (8) + b1    -> g_gcomb
//   385..392 : W2 fp16 transpose   -> g_W2h ([n][k])
//   393      : tile counter reset
// ---------------------------------------------------------------------------
__global__ __launch_bounds__(256) void prep_kernel(
    const float* __restrict__ ue, const float* __restrict__ te,
    const float* __restrict__ ge, const float* __restrict__ W1,
    const float* __restrict__ b1, const float* __restrict__ W2) {
    __shared__ float s_in[8 * EE];
    const int bid = blockIdx.x;
    const int tid = threadIdx.x;

    if (bid < 385) {
        const float* src;
        float* dst;
        const float* W;
        bool addb = false;
        if (bid < 128) {
            src = ue + bid * 8 * EE;  dst = g_ue_proj + bid * 8 * HH;  W = W1;
        } else if (bid < 384) {
            int r = bid - 128;
            src = te + r * 8 * EE;    dst = g_te_proj + r * 8 * HH;
            W = W1 + EE * HH;
        } else {
            src = ge;  dst = g_gcomb;  W = W1 + 2 * EE * HH;  addb = true;
        }
        for (int i = tid; i < 8 * EE; i += 256) s_in[i] = src[i];
        __syncthreads();

        const int col = tid & 127;
        const int rh  = (tid >> 7) * 4;              // rows rh..rh+3
        float bb = addb ? b1[col] : 0.0f;
        float a0 = bb, a1 = bb, a2 = bb, a3 = bb;
#pragma unroll 4
        for (int e = 0; e < EE; e++) {
            float w = W[e * HH + col];
            a0 = fmaf(s_in[(rh + 0) * EE + e], w, a0);
            a1 = fmaf(s_in[(rh + 1) * EE + e], w, a1);
            a2 = fmaf(s_in[(rh + 2) * EE + e], w, a2);
            a3 = fmaf(s_in[(rh + 3) * EE + e], w, a3);
        }
        dst[(rh + 0) * HH + col] = a0;
        dst[(rh + 1) * HH + col] = a1;
        dst[(rh + 2) * HH + col] = a2;
        dst[(rh + 3) * HH + col] = a3;
    } else if (bid < 393) {
        const int n0 = (bid - 385) * 16 + (tid >> 7) * 8;
        const int k  = tid & 127;
#pragma unroll
        for (int j = 0; j < 8; j++)
            g_W2h[(n0 + j) * HH + k] = __float2half_rn(W2[k * HH + n0 + j]);
    } else {
        if (tid == 0) g_tile_ctr = 0;
    }
}

// ---------------------------------------------------------------------------
// Main fused kernel — R12/R15 structure: warp-autonomous 16-row strips,
// 2 CTAs/SM, f16x2-tanh h1 gelu, tanh.approx.f32 epilogue gelu.
// ---------------------------------------------------------------------------
static constexpr int ST      = 136;                 // row stride in fp16
static constexpr int STB     = ST * 2;              // 272 bytes
static constexpr int OFF_B   = 0;                   // 128 rows x STB = 34816
static constexpr int OFF_A   = 34816;               // 8 warps x 16 rows x STB
static constexpr int OFF_BW  = OFF_A + 34816;       // 128 x float2 (b2, W3)
static constexpr int SMEM_MAIN = OFF_BW + 1024;     // ~70.7 KB -> 2 CTAs/SM

__global__ __launch_bounds__(256, 2) void pairwise_main(
    const float* __restrict__ b2, const float* __restrict__ W3,
    const float* __restrict__ b3, float* __restrict__ out) {
    extern __shared__ char smem[];
    const uint32_t smem_base = smem_to_u32(smem);
    const int tid  = threadIdx.x;
    const int wid  = tid >> 5;
    const int lane = tid & 31;

    // Stage W2 (padded rows) + packed (b2, W3) pairs into SMEM, once.
    {
        const uint4* sb = (const uint4*)g_W2h;
        for (int i = tid; i < 2048; i += 256) {       // 128 rows x 16 uint4
            int r = i >> 4, c = i & 15;
            *(uint4*)(smem + OFF_B + r * STB + c * 16) = sb[i];
        }
        if (tid < 128)
            *(float2*)(smem + OFF_BW + tid * 8) = make_float2(b2[tid], W3[tid]);
    }
    const float bias3 = b3[0];
    __syncthreads();                                 // the only block barrier

    // Per-warp A buffer base
    const uint32_t abase_u = smem_base + OFF_A + wid * 16 * STB;
    char* abuf = smem + OFF_A + wid * 16 * STB + lane * 8;

    // ldmatrix lane addressing (within warp-private 16-row A / shared B)
    const uint32_t a_addr0 = abase_u + (lane & 15) * STB + ((lane >> 4) * 8) * 2;
    const int b_r = ((lane >> 4) & 1) * 8 + (lane & 7);
    const int b_k = ((lane >> 3) & 1) * 8;

    for (;;) {
        int s;
        if (lane == 0) s = atomicAdd(&g_tile_ctr, 1);
        s = __shfl_sync(0xffffffffu, s, 0);
        if (s >= NUM_STRIPS) break;

        const int b  = s >> 11;
        const int u  = (s >> 4) & 127;
        const int tq = s & 15;

        // per-lane uc columns 4l..4l+3 (registers)
        const float4 uev = *(const float4*)(g_ue_proj + (b * UU + u) * HH + (lane << 2));
        const float4 gcv = *(const float4*)(g_gcomb + b * HH + (lane << 2));
        const float4 ucv = make_float4(uev.x + gcv.x, uev.y + gcv.y,
                                       uev.z + gcv.z, uev.w + gcv.w);

        // ---- h1: 16 rows, coalesced LDG + f16x2-tanh gelu -> private A ----
        const float* tebase =
            g_te_proj + ((size_t)(b * TT + tq * 16)) * HH + (lane << 2);
#pragma unroll
        for (int r = 0; r < 16; r++) {
            float4 tv = *(const float4*)(tebase + (size_t)r * HH);
            uint32_t y01 = gelu2_h2(tv.x + ucv.x, tv.y + ucv.y);
            uint32_t y23 = gelu2_h2(tv.z + ucv.z, tv.w + ucv.w);
            *(uint2*)(abuf + r * STB) = make_uint2(y01, y23);
        }
        __syncwarp();

        // ---- GEMM: 16x128x128, acc[16 n-tiles][4] in regs ----
        float acc[16][4];
#pragma unroll
        for (int nt = 0; nt < 16; nt++)
#pragma unroll
            for (int i = 0; i < 4; i++) acc[nt][i] = 0.0f;

#pragma unroll
        for (int kt = 0; kt < 8; kt++) {
            const int k0 = kt * 16;
            uint32_t a[4];
            ldmatrix_x4(a[0], a[1], a[2], a[3], a_addr0 + k0 * 2);
            uint32_t bh[16][2];
#pragma unroll
            for (int np = 0; np < 8; np++) {          // pairs of n-tiles
                uint32_t baddr =
                    smem_base + OFF_B + (b_r + np * 16) * STB + (k0 + b_k) * 2;
                ldmatrix_x4(bh[np * 2][0], bh[np * 2][1],
                            bh[np * 2 + 1][0], bh[np * 2 + 1][1], baddr);
            }
#pragma unroll
            for (int nt = 0; nt < 16; nt++)
                mma_fp16(acc[nt], a, bh[nt]);
        }

        // ---- Epilogue: gelu(acc + b2) . W3 over N=128, direct STG ----
        float s0 = 0.0f, s1 = 0.0f;
#pragma unroll
        for (int nt = 0; nt < 16; nt++) {
            const int c0 = nt * 8 + 2 * (lane & 3);
            float4 bw = *(const float4*)(smem + OFF_BW + c0 * 8);
            s0 = fmaf(gelu_f(acc[nt][0] + bw.x), bw.y, s0);
            s0 = fmaf(gelu_f(acc[nt][1] + bw.z), bw.w, s0);
            s1 = fmaf(gelu_f(acc[nt][2] + bw.x), bw.y, s1);
            s1 = fmaf(gelu_f(acc[nt][3] + bw.z), bw.w, s1);
        }
        s0 += __shfl_xor_sync(0xffffffffu, s0, 1);
        s0 += __shfl_xor_sync(0xffffffffu, s0, 2);
        s1 += __shfl_xor_sync(0xffffffffu, s1, 1);
        s1 += __shfl_xor_sync(0xffffffffu, s1, 2);
        if ((lane & 3) == 0) {
            const int t0 = tq * 16 + (lane >> 2);
            float* o = out + (size_t)b * (UU * TT) + u * TT;
            o[t0]     = s0 + bias3;
            o[t0 + 8] = s1 + bias3;
        }
    }
}

// ---------------------------------------------------------------------------
// Launch
// ---------------------------------------------------------------------------
extern "C" void kernel_launch(void* const* d_in, const int* in_sizes, int n_in,
                              void* d_out, int out_size) {
    (void)in_sizes; (void)n_in; (void)out_size;
    const float* ue = (const float*)d_in[0];
    const float* te = (const float*)d_in[1];
    const float* ge = (const float*)d_in[2];
    const float* W1 = (const float*)d_in[3];
    const float* b1 = (const float*)d_in[4];
    const float* W2 = (const float*)d_in[5];
    const float* b2 = (const float*)d_in[6];
    const float* W3 = (const float*)d_in[7];
    const float* b3 = (const float*)d_in[8];
    float* out = (float*)d_out;

    cudaFuncSetAttribute(pairwise_main,
                         cudaFuncAttributeMaxDynamicSharedMemorySize, SMEM_MAIN);

    prep_kernel<<<394, 256>>>(ue, te, ge, W1, b1, W2);
    pairwise_main<<<304, 256, SMEM_MAIN>>>(b2, W3, b3, out);
}